// round 14
// baseline (speedup 1.0000x reference)
#include <cuda_runtime.h>
#include <cuda_fp16.h>
#include <cstdint>

#define DEV __device__ __forceinline__

namespace {

constexpr int LEADS = 12;
constexpr int FIN   = 512;
constexpr int HID   = 256;
constexpr int OUTF  = 128;
constexpr int TOTAL_B = 16384;
constexpr int TOTAL_ROWS = TOTAL_B * LEADS;   // 196608

constexpr int SAMP = 10;       // samples per CTA -> 120 rows, pad to 128
constexpr int NT   = 512;      // 16 warps, 64x32 warp tiles (2m x 8n)
constexpr int KC   = 64;       // K halves per streamed chunk (4 x k16 mma steps)

// strides in halves. ldmatrix conflict-free: stride_words mod 8 == 4.
// SA/SB = 72 -> 36 words (36%8=4 ok). SHH = 264 -> 132 words (132%8=4 ok).
constexpr int SA  = 72;        // staged A (X) row stride
constexpr int SB  = 72;        // staged B (W^T) row stride
constexpr int SHH = 264;       // H buffer row stride

constexpr int XBUF = 128 * SA;     // 9216 halves per buffer
constexpr int WBUF = 256 * SB;     // 18432 halves per buffer (36864 B)

// SMEM layout (halves)
constexpr int OFF_HH = 0;                       // 128 x 264 = 33792
constexpr int OFF_XS = 128 * SHH;               // 2 x XBUF
constexpr int OFF_WS = OFF_XS + 2 * XBUF;       // 2 x WBUF
constexpr int SMEM_HALVES = OFF_WS + 2 * WBUF;  // 89088
constexpr int SMEM_BYTES  = SMEM_HALVES * 2;    // 178176 B

// Weight scratch: pre-transposed fp16 panels in EXACT SMEM chunk layout (incl. pad)
constexpr int WCH  = 256 * SB;   // 18432 halves per chunk (W1/W2)
constexpr int WCH3 = 128 * SB;   // 9216 halves per chunk (W3)
__device__ __half g_w1t[(FIN / KC) * WCH];   // 8 chunks
__device__ __half g_w2t[(HID / KC) * WCH];   // 4 chunks
__device__ __half g_w3t[(HID / KC) * WCH3];  // 4 chunks

// ---- compile-time normalized adjacency (matches reference _norm_adj) ----
constexpr double csqrt(double x) {
  double g = x > 1.0 ? x : 1.0;
  for (int i = 0; i < 64; i++) g = 0.5 * (g + x / g);
  return g;
}
struct AMt { float a[12][12]; };
constexpr AMt make_am() {
  AMt m{};
  const int ci[15] = {0,0,1,0,1,2,0,1,1,2,6,7,8,9,10};
  const int cj[15] = {1,2,2,3,3,3,4,4,5,5,7,8,9,10,11};
  double ae[12][12] = {};
  for (int p = 0; p < 15; p++) { ae[ci[p]][cj[p]] = 1.0; ae[cj[p]][ci[p]] = 1.0; }
  for (int i = 0; i < 12; i++) ae[i][i] = 2.0;
  double deg[12] = {};
  for (int i = 0; i < 12; i++)
    for (int j = 0; j < 12; j++) deg[i] += ae[i][j];
  for (int i = 0; i < 12; i++)
    for (int j = 0; j < 12; j++)
      m.a[i][j] = (float)(ae[i][j] / (csqrt(deg[i]) * csqrt(deg[j])));
  return m;
}
__device__ constexpr AMt AMC = make_am();

DEV uint32_t h2u(__half2 h) { return *reinterpret_cast<uint32_t*>(&h); }

DEV void mma16(float d[4], const uint32_t a[4], uint32_t b0, uint32_t b1) {
  asm volatile(
    "mma.sync.aligned.m16n8k16.row.col.f32.f16.f16.f32 "
    "{%0,%1,%2,%3},{%4,%5,%6,%7},{%8,%9},{%0,%1,%2,%3};"
    : "+f"(d[0]), "+f"(d[1]), "+f"(d[2]), "+f"(d[3])
    : "r"(a[0]), "r"(a[1]), "r"(a[2]), "r"(a[3]), "r"(b0), "r"(b1));
}

DEV void ldm_x4(uint32_t r[4], uint32_t saddr) {
  asm volatile("ldmatrix.sync.aligned.m8n8.x4.shared.b16 {%0,%1,%2,%3}, [%4];"
               : "=r"(r[0]), "=r"(r[1]), "=r"(r[2]), "=r"(r[3]) : "r"(saddr));
}

DEV void cpa16(uint32_t dst, const void* src) {
  asm volatile("cp.async.ca.shared.global [%0], [%1], 16;"
               :: "r"(dst), "l"(src) : "memory");
}
#define CPA_COMMIT() asm volatile("cp.async.commit_group;" ::: "memory")
#define CPA_WAIT0()  asm volatile("cp.async.wait_group 0;" ::: "memory")

// Warp-level 64 x (NTILES*8) GEMM over one KC=64 chunk (4 k16 steps).
// aAddr/bAddr: SMEM byte addresses already including per-lane ldmatrix offsets.
// SAB/SBB: row strides in BYTES (compile-time -> LDSM [R+imm]).
template<int NTILES, int SAB, int SBB>
DEV void gemm_chunk(uint32_t aAddr, uint32_t bAddr, float acc[4][4][4]) {
  #pragma unroll
  for (int k0 = 0; k0 < KC; k0 += 16) {
    uint32_t a[4][4];
    #pragma unroll
    for (int mi = 0; mi < 4; mi++)
      ldm_x4(a[mi], aAddr + mi * 16 * SAB + k0 * 2);
    uint32_t b[NTILES][2];
    #pragma unroll
    for (int np = 0; np < NTILES / 2; np++) {
      uint32_t t[4];
      ldm_x4(t, bAddr + np * 16 * SBB + k0 * 2);
      b[2 * np][0] = t[0]; b[2 * np][1] = t[1];
      b[2 * np + 1][0] = t[2]; b[2 * np + 1][1] = t[3];
    }
    #pragma unroll
    for (int nj = 0; nj < NTILES; nj++)
      #pragma unroll
      for (int mi = 0; mi < 4; mi++)
        mma16(acc[mi][nj], a[mi], b[nj][0], b[nj][1]);
  }
}

// ---- one-shot: transpose + fp16-convert weights into panel-layout scratch ----
__global__ void conv_w_kernel(const float* __restrict__ W1,
                              const float* __restrict__ W2,
                              const float* __restrict__ W3) {
  int id = blockIdx.x * blockDim.x + threadIdx.x;   // 0 .. 131071
  if (id < FIN * HID) {            // W1: [512][256]
    int k = id >> 8, n = id & 255;
    g_w1t[(k >> 6) * WCH + n * SB + (k & 63)] = __float2half(W1[id]);
  }
  if (id < HID * HID) {            // W2: [256][256]
    int k = id >> 8, n = id & 255;
    g_w2t[(k >> 6) * WCH + n * SB + (k & 63)] = __float2half(W2[id]);
  }
  if (id < HID * OUTF) {           // W3: [256][128]
    int k = id >> 7, n = id & 127;
    g_w3t[(k >> 6) * WCH3 + n * SB + (k & 63)] = __float2half(W3[id]);
  }
}

__global__ void __launch_bounds__(NT, 1)
ecg_fused_kernel(const float* __restrict__ x,
                 const float* __restrict__ b1,
                 const float* __restrict__ b2,
                 const float* __restrict__ b3,
                 float* __restrict__ out)
{
  extern __shared__ __align__(16) __half smh[];
  __half* Hh = smh + OFF_HH;
  __half* Xs = smh + OFF_XS;
  __half* Ws = smh + OFF_WS;

  const int tid  = threadIdx.x;
  const int lane = tid & 31;
  const int wid  = tid >> 5;
  const int wm   = wid >> 3;   // 0..1 (64-row blocks)
  const int wn   = wid & 7;    // 0..7 (col blocks)
  const int s0    = blockIdx.x * SAMP;
  const int nsamp = min(SAMP, TOTAL_B - s0);
  const int row0  = s0 * LEADS;

  const int l7 = lane & 7, lb8 = (lane >> 3) & 1, lb16 = lane >> 4;

  // SMEM byte addresses
  const uint32_t hh_addr = (uint32_t)__cvta_generic_to_shared(Hh);
  const uint32_t xs_addr = (uint32_t)__cvta_generic_to_shared(Xs);
  const uint32_t ws_addr = (uint32_t)__cvta_generic_to_shared(Ws);

  // per-lane ldmatrix offsets (bytes)
  const uint32_t laneA_sa  = (uint32_t)((lb8 * 8 + l7) * SA  + lb16 * 8) * 2;
  const uint32_t laneA_shh = (uint32_t)((lb8 * 8 + l7) * SHH + lb16 * 8) * 2;
  const uint32_t laneB_sb  = (uint32_t)((lb16 * 8 + l7) * SB + lb8 * 8) * 2;

  float acc[4][4][4];

  auto zero_acc = [&]() {
    #pragma unroll
    for (int mi = 0; mi < 4; mi++)
      #pragma unroll
      for (int nj = 0; nj < 4; nj++)
        #pragma unroll
        for (int q = 0; q < 4; q++) acc[mi][nj][q] = 0.f;
  };

  // Async copy one pre-laid-out W chunk into Ws buffer `buf`. n16 = 16B units.
  auto issue_w = [&](const __half* gsrc, int buf, int n16) {
    uint32_t base = ws_addr + (uint32_t)buf * (WBUF * 2);
    const char* src = reinterpret_cast<const char*>(gsrc);
    for (int i = tid; i < n16; i += NT)
      cpa16(base + i * 16, src + i * 16);
    CPA_COMMIT();
  };

  // Epilogue: fp32 accumulators -> fp16 into Hh
  auto store_acc = [&](int wcols, int ntiles) {
    const int g = lane >> 2, t2 = (lane & 3) * 2;
    #pragma unroll
    for (int mi = 0; mi < 4; mi++)
      #pragma unroll
      for (int nj = 0; nj < 4; nj++) {
        if (nj >= ntiles) break;
        int row = wm * 64 + mi * 16 + g;
        int col = wn * wcols + nj * 8 + t2;
        *reinterpret_cast<__half2*>(Hh + row * SHH + col) =
            __floats2half2_rn(acc[mi][nj][0], acc[mi][nj][1]);
        *reinterpret_cast<__half2*>(Hh + (row + 8) * SHH + col) =
            __floats2half2_rn(acc[mi][nj][2], acc[mi][nj][3]);
      }
  };

  // Lead-mix + bias + relu, fp16 in place in Hh (column pairs)
  auto mixH = [&](const float* bias) {
    const int ntask = nsamp * (HID / 2);
    for (int tk = tid; tk < ntask; tk += NT) {
      int s = tk >> 7, cp = tk & 127;
      __half* base = Hh + (s * LEADS) * SHH + cp * 2;
      float2 v[12];
      #pragma unroll
      for (int l = 0; l < 12; l++)
        v[l] = __half22float2(*reinterpret_cast<__half2*>(base + l * SHH));
      float bx = bias[cp * 2], by = bias[cp * 2 + 1];
      #pragma unroll
      for (int n = 0; n < 12; n++) {
        float hx = bx, hy = by;
        #pragma unroll
        for (int m = 0; m < 12; m++) {
          if (AMC.a[n][m] != 0.f) {
            hx = fmaf(AMC.a[n][m], v[m].x, hx);
            hy = fmaf(AMC.a[n][m], v[m].y, hy);
          }
        }
        *reinterpret_cast<__half2*>(base + n * SHH) =
            __floats2half2_rn(fmaxf(hx, 0.f), fmaxf(hy, 0.f));
      }
    }
  };

  // ======================= Layer 1: X(128x512) @ W1(512x256) =======================
  {
    zero_acc();
    float4 px[4];

    // X stage: 128 rows x 64 halves -> 2048 float4 source reads, 4/thread
    auto ldx = [&](int kb) {
      #pragma unroll
      for (int i = 0; i < 4; i++) {
        int idx = tid + i * NT;
        int xr = idx >> 4, gq = idx & 15;
        int gr = row0 + xr;
        px[i] = (gr < TOTAL_ROWS)
                    ? *reinterpret_cast<const float4*>(x + (size_t)gr * FIN + kb + gq * 4)
                    : make_float4(0.f, 0.f, 0.f, 0.f);
      }
    };
    auto stx = [&](int buf) {
      #pragma unroll
      for (int i = 0; i < 4; i++) {
        int idx = tid + i * NT;
        int xr = idx >> 4, gq = idx & 15;
        uint2 u;
        u.x = h2u(__floats2half2_rn(px[i].x, px[i].y));
        u.y = h2u(__floats2half2_rn(px[i].z, px[i].w));
        *reinterpret_cast<uint2*>(Xs + buf * XBUF + xr * SA + gq * 4) = u;
      }
    };

    ldx(0);
    issue_w(g_w1t, 0, 2304);
    stx(0);
    CPA_WAIT0();
    __syncthreads();
    constexpr int NC = FIN / KC;   // 8 chunks
    for (int ck = 0; ck < NC; ck++) {
      if (ck + 1 < NC) { ldx((ck + 1) * KC); issue_w(g_w1t + (ck + 1) * WCH, (ck + 1) & 1, 2304); }
      gemm_chunk<4, SA * 2, SB * 2>(
          xs_addr + (uint32_t)((ck & 1) * XBUF + wm * 64 * SA) * 2 + laneA_sa,
          ws_addr + (uint32_t)((ck & 1) * WBUF + wn * 32 * SB) * 2 + laneB_sb, acc);
      if (ck + 1 < NC) stx((ck + 1) & 1);
      CPA_WAIT0();
      __syncthreads();
    }
    // prefetch L2's first W chunk; lands during store_acc + mixH
    issue_w(g_w2t, 0, 2304);
    store_acc(32, 4);
    __syncthreads();
    mixH(b1);
    CPA_WAIT0();
    __syncthreads();
  }

  // ======================= Layer 2: H(128x256) @ W2(256x256) =======================
  {
    zero_acc();
    constexpr int NC2 = HID / KC;   // 4 chunks
    for (int ck = 0; ck < NC2; ck++) {
      if (ck + 1 < NC2) issue_w(g_w2t + (ck + 1) * WCH, (ck + 1) & 1, 2304);
      gemm_chunk<4, SHH * 2, SB * 2>(
          hh_addr + (uint32_t)(wm * 64 * SHH + ck * KC) * 2 + laneA_shh,
          ws_addr + (uint32_t)((ck & 1) * WBUF + wn * 32 * SB) * 2 + laneB_sb, acc);
      CPA_WAIT0();
      __syncthreads();
    }
    // prefetch L3's first W chunk
    issue_w(g_w3t, 0, 1152);
    store_acc(32, 4);
    __syncthreads();
    mixH(b2);
    CPA_WAIT0();
    __syncthreads();
  }

  // ======================= Layer 3: H(128x256) @ W3(256x128) + pool =======================
  {
    zero_acc();
    constexpr int NC3 = HID / KC;   // 4 chunks
    for (int ck = 0; ck < NC3; ck++) {
      if (ck + 1 < NC3) issue_w(g_w3t + (ck + 1) * WCH3, (ck + 1) & 1, 1152);
      gemm_chunk<2, SHH * 2, SB * 2>(
          hh_addr + (uint32_t)(wm * 64 * SHH + ck * KC) * 2 + laneA_shh,
          ws_addr + (uint32_t)((ck & 1) * WBUF + wn * 16 * SB) * 2 + laneB_sb, acc);
      CPA_WAIT0();
      __syncthreads();
    }
    store_acc(16, 2);
    __syncthreads();

    // Final: lead-mix + b3, mean/max pool over leads, write (B, 2*OUTF)
    const int ntask = nsamp * (OUTF / 2);
    for (int tk = tid; tk < ntask; tk += NT) {
      int s = tk >> 6, cp = tk & 63;
      const __half* base = Hh + (s * LEADS) * SHH + cp * 2;
      float2 v[12];
      #pragma unroll
      for (int l = 0; l < 12; l++)
        v[l] = __half22float2(*reinterpret_cast<const __half2*>(base + l * SHH));
      float bx = b3[cp * 2], by = b3[cp * 2 + 1];
      float meanx = 0.f, meany = 0.f;
      float mxx = __int_as_float(0xff800000), mxy = mxx;
      #pragma unroll
      for (int n = 0; n < 12; n++) {
        float hx = bx, hy = by;
        #pragma unroll
        for (int m = 0; m < 12; m++) {
          if (AMC.a[n][m] != 0.f) {
            hx = fmaf(AMC.a[n][m], v[m].x, hx);
            hy = fmaf(AMC.a[n][m], v[m].y, hy);
          }
        }
        meanx += hx; meany += hy;
        mxx = fmaxf(mxx, hx); mxy = fmaxf(mxy, hy);
      }
      size_t ob = (size_t)(s0 + s) * (2 * OUTF);
      *reinterpret_cast<float2*>(out + ob + cp * 2) =
          make_float2(meanx * (1.f / 12.f), meany * (1.f / 12.f));
      *reinterpret_cast<float2*>(out + ob + OUTF + cp * 2) = make_float2(mxx, mxy);
    }
  }
}

} // anonymous namespace

extern "C" void kernel_launch(void* const* d_in, const int* in_sizes, int n_in,
                              void* d_out, int out_size) {
  const float* x  = (const float*)d_in[0];
  const float* W1 = (const float*)d_in[1];
  const float* b1 = (const float*)d_in[2];
  const float* W2 = (const float*)d_in[3];
  const float* b2 = (const float*)d_in[4];
  const float* W3 = (const float*)d_in[5];
  const float* b3 = (const float*)d_in[6];
  float* out = (float*)d_out;

  // one-shot weight transpose+convert into panel-layout scratch
  conv_w_kernel<<<(FIN * HID + 255) / 256, 256>>>(W1, W2, W3);

  cudaFuncSetAttribute(ecg_fused_kernel,
                       cudaFuncAttributeMaxDynamicSharedMemorySize, SMEM_BYTES);

  const int grid = (TOTAL_B + SAMP - 1) / SAMP;   // 1639
  ecg_fused_kernel<<<grid, NT, SMEM_BYTES>>>(x, b1, b2, b3, out);
}